// round 14
// baseline (speedup 1.0000x reference)
#include <cuda_runtime.h>

// ---------------------------------------------------------------------------
// ComputeLoss (YOLOv5-style), fixed shapes:
//   p0: (32,255,80,80)  p1: (32,255,40,40)  p2: (32,255,20,20)
//   targets: (1024,6) = [img, cls, cx, cy, w, h]
// Output: one float32 scalar.
//
// 3 launches:
//   k_main : dense softplus(obj) stream + ONE WARP PER (lev,m,a) GROUP.
//            The <=3 flagged cells (center, x-, y-neighbor) are processed by
//            lanes 0/1/2 in parallel. Streaming (__ldcs) gathers, 6 blocks/SM.
//   k_zero : 64 blocks zero the listed g_objmax cells
//   k_fin  : finalize scalar, reset state.
// ---------------------------------------------------------------------------

#define NIMG 32
#define NA   3
#define NCLS 80
#define MT   1024
#define CELLS0 (NIMG*NA*80*80)    // 614400
#define CELLS1 (NIMG*NA*40*40)    // 153600
#define CELLS2 (NIMG*NA*20*20)    // 38400
#define CELLS_TOT (CELLS0+CELLS1+CELLS2)   // 806400
#define TOTCELLS (3*3*MT*3)       // list capacity: 3 cells per group max

#define OBJ_GROUPS (CELLS_TOT/4)              // 201600 float4 groups
#define OBJ_BLOCKS ((OBJ_GROUPS + 255)/256)   // 788
#define NGRP (3*MT*NA)                        // 9216 groups (lev,m,a)
#define CAND_BLOCKS (NGRP/8)                  // 1152
#define GRID (OBJ_BLOCKS + CAND_BLOCKS)       // 1940

#define FULLM 0xffffffffu

__constant__ float c_anch[3][3][2] = {
  {{1.25f,1.625f},{2.0f,3.75f},{4.125f,2.875f}},
  {{1.875f,3.8125f},{3.875f,2.8125f},{3.6875f,7.4375f}},
  {{3.625f,2.8125f},{4.875f,6.1875f},{11.65625f,10.1875f}}
};

// per-cell objectness max (float bits >= 0). Zero at module load; k_zero
// zeroes every touched cell each launch (list-driven).
__device__ unsigned g_objmax[CELLS_TOT];
__device__ int   g_cellList[TOTCELLS];
__device__ int   g_nflag;
// [0..2]=lbox, [3..5]=cls, [6..8]=obj_softplus, [9..11]=obj_corr
__device__ double g_acc[12];
__device__ int g_cnt[3];

__device__ __forceinline__ float sp_(float x){          // softplus (fast-math)
    return fmaxf(x, 0.f) + __logf(1.f + __expf(-fabsf(x)));
}
__device__ __forceinline__ float sig_(float x){
    return 1.f / (1.f + __expf(-x));
}

__device__ __forceinline__ float giou_(float px,float py,float pw,float ph,
                                       float gx,float gy,float gw,float gh){
    const float eps = 1e-7f;
    float px1 = px - pw*0.5f, py1 = py - ph*0.5f;
    float px2 = px + pw*0.5f, py2 = py + ph*0.5f;
    float qx1 = gx - gw*0.5f, qy1 = gy - gh*0.5f;
    float qx2 = gx + gw*0.5f, qy2 = gy + gh*0.5f;
    float iw = fmaxf(fminf(px2,qx2) - fmaxf(px1,qx1), 0.f);
    float ih = fmaxf(fminf(py2,qy2) - fmaxf(py1,qy1), 0.f);
    float inter = iw * ih;
    float uni = pw*ph + gw*gh - inter + eps;
    float iou = inter / uni;
    float cw = fmaxf(px2,qx2) - fminf(px1,qx1);
    float ch = fmaxf(py2,qy2) - fminf(py1,qy1);
    float ca = cw*ch + eps;
    return iou - (ca - uni) / ca;
}

// warp butterfly sum (warp-wide, convergent)
__device__ __forceinline__ float wsum_(float v){
    #pragma unroll
    for (int d = 16; d; d >>= 1) v += __shfl_xor_sync(FULLM, v, d);
    return v;
}

// ============================ Kernel A ======================================
__global__ __launch_bounds__(256, 6) void k_main(
        const float* __restrict__ p0, const float* __restrict__ p1,
        const float* __restrict__ p2, const float* __restrict__ tg)
{
    const int tid  = threadIdx.x;
    const int lane = tid & 31;
    const int wib  = tid >> 5;

    if (blockIdx.x < OBJ_BLOCKS){
        // ---------------- dense objectness softplus sum -------------------
        // warps are level-homogeneous (boundaries at g = 153600, 192000)
        int g = blockIdx.x * 256 + tid;
        float s = 0.f;
        int lev = 2;
        if (g < OBJ_GROUPS){
            int cell = g * 4;
            int base, HW;
            const float* P;
            if (cell < CELLS0){ lev = 0; base = cell;               HW = 6400; P = p0; }
            else if (cell < CELLS0 + CELLS1){ lev = 1; base = cell - CELLS0; HW = 1600; P = p1; }
            else { lev = 2; base = cell - (CELLS0 + CELLS1); HW = 400; P = p2; }
            int n_a = base / HW, hw = base - n_a * HW;
            int n = n_a / 3, a = n_a - n * 3;
            const float4 v = __ldcs(reinterpret_cast<const float4*>(
                P + (size_t)(n*255 + a*85 + 4) * HW + hw));
            s = sp_(v.x) + sp_(v.y) + sp_(v.z) + sp_(v.w);
        }
        s = wsum_(s);
        __shared__ float sh[8];
        if (lane == 0) sh[wib] = s;
        __syncthreads();
        if (tid == 0){
            float t = sh[0]+sh[1]+sh[2]+sh[3]+sh[4]+sh[5]+sh[6]+sh[7];
            atomicAdd(&g_acc[6 + lev], (double)t);
        }
        return;
    }

    // ---------- candidate path: ONE WARP PER (lev, m, a) GROUP ------------
    int gid = ((blockIdx.x - OBJ_BLOCKS) * 256 + tid) >> 5;   // 0..9215
    int lev = gid / (MT * NA);
    int r   = gid - lev * (MT * NA);
    int m   = r / NA;
    int a   = r - m * NA;

    const int W  = (lev==0) ? 80 : ((lev==1) ? 40 : 20);
    const int HW = W * W;
    const float fW = (float)W;

    float t0 = tg[m*6+0];
    float t1 = tg[m*6+1];
    float tx = tg[m*6+2] * fW;
    float ty = tg[m*6+3] * fW;
    float tw = tg[m*6+4] * fW;
    float th = tg[m*6+5] * fW;

    float aw = c_anch[lev][a][0];
    float ah = c_anch[lev][a][1];
    float rw = aw / tw, rh = ah / th;
    float mr = fmaxf(fmaxf(rw, 1.f/rw), fmaxf(rh, 1.f/rh));
    bool bm = mr < 4.0f;    // warp-uniform

    float lbox_c = 0.f, cls_c = 0.f, corr_c = 0.f;
    int cnt_c = 0;
    int myCell = -1;        // lanes 0-2: listed cell (first raiser) or -1

    if (bm){   // warp-uniform branch: all lanes enter together
        int gx0 = (int)floorf(tx);
        int gy0 = (int)floorf(ty);
        float remx = tx - (float)gx0;
        float remy = ty - (float)gy0;

        // x neighbor: exactly one of left/right may fire (rem==0.5 -> none)
        bool xleft = remx < 0.5f;
        bool fxv = xleft ? (tx > 1.0f) : ((remx > 0.5f) && (tx < fW - 1.0f));
        int  gx1 = xleft ? gx0 - 1 : gx0 + 1;
        // y neighbor
        bool ytop = remy < 0.5f;
        bool fyv = ytop ? (ty > 1.0f) : ((remy > 0.5f) && (ty < fW - 1.0f));
        int  gy1 = ytop ? gy0 - 1 : gy0 + 1;

        int gxc0 = min(max(gx0, 0), W-1), gyc0 = min(max(gy0, 0), W-1);
        int gxc1 = min(max(gx1, 0), W-1), gyc1 = min(max(gy1, 0), W-1);
        int img = min(max((int)t0, 0), NIMG-1);
        int cls = (int)t1;

        const float* P = (lev==0) ? p0 : ((lev==1) ? p1 : p2);
        const float* plane = P + (size_t)(img*255 + a*85) * HW;
        const float* b0 = plane + gyc0 * W + gxc0;   // center
        const float* b1 = plane + gyc0 * W + gxc1;   // x-neighbor (same row)
        const float* b2 = plane + gyc1 * W + gxc0;   // y-neighbor (same col)

        // ---- class logits for up to 3 cells; lane covers c, c+32, c+64 ----
        float s0=0.f, s1=0.f, s2=0.f, p0v=0.f, p1v=0.f, p2v=0.f;
        #pragma unroll
        for (int i = 0; i < 3; i++){
            int c = lane + 32*i;
            if (c < NCLS){
                size_t o = (size_t)(5 + c) * HW;
                float v0 = __ldcs(b0 + o);
                float v1 = fxv ? __ldcs(b1 + o) : 0.f;
                float v2 = fyv ? __ldcs(b2 + o) : 0.f;
                s0 += sp_(v0); if (c == cls) p0v = v0;
                if (fxv){ s1 += sp_(v1); if (c == cls) p1v = v1; }
                if (fyv){ s2 += sp_(v2); if (c == cls) p2v = v2; }
            }
        }
        // ---- box+obj logits: lanes 0-4 cell0, 8-12 cellx, 16-20 celly ----
        float opv = 0.f;
        if (lane < 5)                            opv = __ldcs(b0 + (size_t)lane * HW);
        else if (lane >= 8  && lane < 13 && fxv) opv = __ldcs(b1 + (size_t)(lane-8)  * HW);
        else if (lane >= 16 && lane < 21 && fyv) opv = __ldcs(b2 + (size_t)(lane-16) * HW);

        s0 = wsum_(s0); p0v = wsum_(p0v);
        s1 = wsum_(s1); p1v = wsum_(p1v);
        s2 = wsum_(s2); p2v = wsum_(p2v);

        // ---- per-lane cell epilogue: lane k (0..2) owns cell k ----------
        int kk = (lane < 3) ? lane : 0;
        float q0 = __shfl_sync(FULLM, opv, kk*8 + 0);
        float q1 = __shfl_sync(FULLM, opv, kk*8 + 1);
        float q2 = __shfl_sync(FULLM, opv, kk*8 + 2);
        float q3 = __shfl_sync(FULLM, opv, kk*8 + 3);
        float xob= __shfl_sync(FULLM, opv, kk*8 + 4);

        bool kvalid = (lane == 0) || (lane == 1 && fxv) || (lane == 2 && fyv);
        float lb = 0.f, lc = 0.f, co = 0.f;

        if (kvalid){
            float gox = (kk == 1) ? (tx - (float)gx1) : remx;
            float goy = (kk == 2) ? (ty - (float)gy1) : remy;
            int   cx  = (kk == 1) ? gxc1 : gxc0;
            int   cy  = (kk == 2) ? gyc1 : gyc0;
            float ssum = (kk==0) ? s0 : ((kk==1) ? s1 : s2);
            float pick = (kk==0) ? p0v : ((kk==1) ? p1v : p2v);

            float px = sig_(q0) * 2.f - 0.5f;
            float py = sig_(q1) * 2.f - 0.5f;
            float sw = sig_(q2) * 2.f;
            float sh2= sig_(q3) * 2.f;
            float pw = sw * sw * aw;
            float ph = sh2 * sh2 * ah;
            float gi = giou_(px, py, pw, ph, gox, goy, tw, th);
            lb = 1.f - gi;
            lc = ssum - pick;

            float ov = fmaxf(gi, 0.f);
            if (ov > 0.f){
                int lvoff = (lev==0) ? 0 : ((lev==1) ? CELLS0 : (CELLS0+CELLS1));
                int cell = lvoff + (img*3 + a) * HW + cy * W + cx;
                unsigned old = atomicMax(&g_objmax[cell], __float_as_uint(ov));
                float oldf = __uint_as_float(old);
                if (ov > oldf){
                    co = (ov - oldf) * xob;          // telescopes to max*x
                    if (old == 0u) myCell = cell;    // first raiser lists cell
                }
            }
        }

        // warp-wide reductions (convergent; non-valid lanes contribute 0)
        lbox_c = wsum_(lb);
        cls_c  = wsum_(lc);
        corr_c = wsum_(co);
        cnt_c  = 1 + (fxv ? 1 : 0) + (fyv ? 1 : 0);
    }

    // ---- block reduction (blocks are level-homogeneous: 3072 % 8 == 0) ----
    __shared__ float sh_lb[8], sh_lc[8], sh_co[8];
    __shared__ int   sh_cn[8], sh_cell[8][3];
    if (lane == 0){
        sh_lb[wib] = lbox_c; sh_lc[wib] = cls_c; sh_co[wib] = corr_c;
        sh_cn[wib] = cnt_c;
    }
    if (lane < 3) sh_cell[wib][lane] = myCell;   // -1 when unused
    __syncthreads();
    if (tid == 0){
        int lev2 = gid / (MT * NA);
        float lb = 0.f, lc = 0.f, co = 0.f; int cn = 0, nv = 0;
        int cells[24];
        #pragma unroll
        for (int i = 0; i < 8; i++){
            lb += sh_lb[i]; lc += sh_lc[i]; co += sh_co[i]; cn += sh_cn[i];
            #pragma unroll
            for (int j = 0; j < 3; j++){
                int c = sh_cell[i][j];
                if (c >= 0) cells[nv++] = c;
            }
        }
        if (cn){
            atomicAdd(&g_acc[lev2],     (double)lb);
            atomicAdd(&g_acc[3 + lev2], (double)lc);
            atomicAdd(&g_cnt[lev2], cn);
        }
        if (co != 0.f) atomicAdd(&g_acc[9 + lev2], (double)co);
        if (nv){
            int bse = atomicAdd(&g_nflag, nv);
            for (int i = 0; i < nv; i++) g_cellList[bse + i] = cells[i];
        }
    }
}

// ============================ Kernel B ======================================
// 64 blocks: zero the listed g_objmax cells. g_nflag is read-only here.
__global__ __launch_bounds__(256) void k_zero()
{
    int n = min(g_nflag, TOTCELLS);
    for (int i = blockIdx.x * 256 + threadIdx.x; i < n; i += 64 * 256)
        g_objmax[g_cellList[i]] = 0u;
}

// ============================ Kernel C ======================================
// 1 warp: finalize scalar and reset all state (strictly after k_zero).
__global__ void k_fin(float* __restrict__ out)
{
    const int tid = threadIdx.x;
    if (tid == 0){
        const double cells[3] = {614400.0, 153600.0, 38400.0};
        const double bal[3]   = {4.0, 1.0, 0.4};
        double lbox = 0.0, lcls = 0.0, lobj = 0.0;
        #pragma unroll
        for (int l = 0; l < 3; l++){
            double cnt = (g_cnt[l] > 0) ? (double)g_cnt[l] : 1.0;
            lbox += g_acc[l] / cnt;
            lcls += g_acc[3 + l] / (cnt * (double)NCLS);
            lobj += ((g_acc[6 + l] - g_acc[9 + l]) / cells[l]) * bal[l];
        }
        out[0] = (float)((0.05 * lbox + 0.5 * lcls + lobj) * 32.0);
    }
    // reset state for next graph replay
    if (tid < 12) g_acc[tid] = 0.0;
    if (tid >= 12 && tid < 15) g_cnt[tid - 12] = 0;
    if (tid == 15) g_nflag = 0;
}

// ---------------------------------------------------------------------------
extern "C" void kernel_launch(void* const* d_in, const int* in_sizes, int n_in,
                              void* d_out, int out_size){
    const float* p0 = (const float*)d_in[0];
    const float* p1 = (const float*)d_in[1];
    const float* p2 = (const float*)d_in[2];
    const float* tg = (const float*)d_in[3];
    float* out = (float*)d_out;
    (void)in_sizes; (void)n_in; (void)out_size;

    k_main<<<GRID, 256>>>(p0, p1, p2, tg);
    k_zero<<<64, 256>>>();
    k_fin <<<1, 32>>>(out);
}

// round 15
// speedup vs baseline: 1.0778x; 1.0778x over previous
#include <cuda_runtime.h>

// ---------------------------------------------------------------------------
// ComputeLoss (YOLOv5-style), fixed shapes:
//   p0: (32,255,80,80)  p1: (32,255,40,40)  p2: (32,255,20,20)
//   targets: (1024,6) = [img, cls, cx, cy, w, h]
// Output: one float32 scalar.
//
// 3 launches:
//   k_main : dense softplus(obj) stream + ONE WARP PER (lev,m,a) GROUP.
//            The <=3 flagged cells (center, x-, y-neighbor) are processed by
//            lanes 0/1/2 in parallel. Default-policy (__ldg) gathers.
//   k_zero : 64 blocks zero the listed g_objmax cells
//   k_fin  : finalize scalar, reset state.
// ---------------------------------------------------------------------------

#define NIMG 32
#define NA   3
#define NCLS 80
#define MT   1024
#define CELLS0 (NIMG*NA*80*80)    // 614400
#define CELLS1 (NIMG*NA*40*40)    // 153600
#define CELLS2 (NIMG*NA*20*20)    // 38400
#define CELLS_TOT (CELLS0+CELLS1+CELLS2)   // 806400
#define TOTCELLS (3*3*MT*3)       // list capacity: 3 cells per group max

#define OBJ_GROUPS (CELLS_TOT/4)              // 201600 float4 groups
#define OBJ_BLOCKS ((OBJ_GROUPS + 255)/256)   // 788
#define NGRP (3*MT*NA)                        // 9216 groups (lev,m,a)
#define CAND_BLOCKS (NGRP/8)                  // 1152
#define GRID (OBJ_BLOCKS + CAND_BLOCKS)       // 1940

#define FULLM 0xffffffffu

__constant__ float c_anch[3][3][2] = {
  {{1.25f,1.625f},{2.0f,3.75f},{4.125f,2.875f}},
  {{1.875f,3.8125f},{3.875f,2.8125f},{3.6875f,7.4375f}},
  {{3.625f,2.8125f},{4.875f,6.1875f},{11.65625f,10.1875f}}
};

// per-cell objectness max (float bits >= 0). Zero at module load; k_zero
// zeroes every touched cell each launch (list-driven).
__device__ unsigned g_objmax[CELLS_TOT];
__device__ int   g_cellList[TOTCELLS];
__device__ int   g_nflag;
// [0..2]=lbox, [3..5]=cls, [6..8]=obj_softplus, [9..11]=obj_corr
__device__ double g_acc[12];
__device__ int g_cnt[3];

__device__ __forceinline__ float sp_(float x){          // softplus (fast-math)
    return fmaxf(x, 0.f) + __logf(1.f + __expf(-fabsf(x)));
}
__device__ __forceinline__ float sig_(float x){
    return 1.f / (1.f + __expf(-x));
}

__device__ __forceinline__ float giou_(float px,float py,float pw,float ph,
                                       float gx,float gy,float gw,float gh){
    const float eps = 1e-7f;
    float px1 = px - pw*0.5f, py1 = py - ph*0.5f;
    float px2 = px + pw*0.5f, py2 = py + ph*0.5f;
    float qx1 = gx - gw*0.5f, qy1 = gy - gh*0.5f;
    float qx2 = gx + gw*0.5f, qy2 = gy + gh*0.5f;
    float iw = fmaxf(fminf(px2,qx2) - fmaxf(px1,qx1), 0.f);
    float ih = fmaxf(fminf(py2,qy2) - fmaxf(py1,qy1), 0.f);
    float inter = iw * ih;
    float uni = pw*ph + gw*gh - inter + eps;
    float iou = inter / uni;
    float cw = fmaxf(px2,qx2) - fminf(px1,qx1);
    float ch = fmaxf(py2,qy2) - fminf(py1,qy1);
    float ca = cw*ch + eps;
    return iou - (ca - uni) / ca;
}

// warp butterfly sum (warp-wide, convergent)
__device__ __forceinline__ float wsum_(float v){
    #pragma unroll
    for (int d = 16; d; d >>= 1) v += __shfl_xor_sync(FULLM, v, d);
    return v;
}

// ============================ Kernel A ======================================
__global__ __launch_bounds__(256, 6) void k_main(
        const float* __restrict__ p0, const float* __restrict__ p1,
        const float* __restrict__ p2, const float* __restrict__ tg)
{
    const int tid  = threadIdx.x;
    const int lane = tid & 31;
    const int wib  = tid >> 5;

    if (blockIdx.x < OBJ_BLOCKS){
        // ---------------- dense objectness softplus sum -------------------
        // warps are level-homogeneous (boundaries at g = 153600, 192000)
        int g = blockIdx.x * 256 + tid;
        float s = 0.f;
        int lev = 2;
        if (g < OBJ_GROUPS){
            int cell = g * 4;
            int base, HW;
            const float* P;
            if (cell < CELLS0){ lev = 0; base = cell;               HW = 6400; P = p0; }
            else if (cell < CELLS0 + CELLS1){ lev = 1; base = cell - CELLS0; HW = 1600; P = p1; }
            else { lev = 2; base = cell - (CELLS0 + CELLS1); HW = 400; P = p2; }
            int n_a = base / HW, hw = base - n_a * HW;
            int n = n_a / 3, a = n_a - n * 3;
            const float4 v = *reinterpret_cast<const float4*>(
                P + (size_t)(n*255 + a*85 + 4) * HW + hw);
            s = sp_(v.x) + sp_(v.y) + sp_(v.z) + sp_(v.w);
        }
        s = wsum_(s);
        __shared__ float sh[8];
        if (lane == 0) sh[wib] = s;
        __syncthreads();
        if (tid == 0){
            float t = sh[0]+sh[1]+sh[2]+sh[3]+sh[4]+sh[5]+sh[6]+sh[7];
            atomicAdd(&g_acc[6 + lev], (double)t);
        }
        return;
    }

    // ---------- candidate path: ONE WARP PER (lev, m, a) GROUP ------------
    int gid = ((blockIdx.x - OBJ_BLOCKS) * 256 + tid) >> 5;   // 0..9215
    int lev = gid / (MT * NA);
    int r   = gid - lev * (MT * NA);
    int m   = r / NA;
    int a   = r - m * NA;

    const int W  = (lev==0) ? 80 : ((lev==1) ? 40 : 20);
    const int HW = W * W;
    const float fW = (float)W;

    float t0 = tg[m*6+0];
    float t1 = tg[m*6+1];
    float tx = tg[m*6+2] * fW;
    float ty = tg[m*6+3] * fW;
    float tw = tg[m*6+4] * fW;
    float th = tg[m*6+5] * fW;

    float aw = c_anch[lev][a][0];
    float ah = c_anch[lev][a][1];
    float rw = aw / tw, rh = ah / th;
    float mr = fmaxf(fmaxf(rw, 1.f/rw), fmaxf(rh, 1.f/rh));
    bool bm = mr < 4.0f;    // warp-uniform

    float lbox_c = 0.f, cls_c = 0.f, corr_c = 0.f;
    int cnt_c = 0;
    int myCell = -1;        // lanes 0-2: listed cell (first raiser) or -1

    if (bm){   // warp-uniform branch: all lanes enter together
        int gx0 = (int)floorf(tx);
        int gy0 = (int)floorf(ty);
        float remx = tx - (float)gx0;
        float remy = ty - (float)gy0;

        // x neighbor: exactly one of left/right may fire (rem==0.5 -> none)
        bool xleft = remx < 0.5f;
        bool fxv = xleft ? (tx > 1.0f) : ((remx > 0.5f) && (tx < fW - 1.0f));
        int  gx1 = xleft ? gx0 - 1 : gx0 + 1;
        // y neighbor
        bool ytop = remy < 0.5f;
        bool fyv = ytop ? (ty > 1.0f) : ((remy > 0.5f) && (ty < fW - 1.0f));
        int  gy1 = ytop ? gy0 - 1 : gy0 + 1;

        int gxc0 = min(max(gx0, 0), W-1), gyc0 = min(max(gy0, 0), W-1);
        int gxc1 = min(max(gx1, 0), W-1), gyc1 = min(max(gy1, 0), W-1);
        int img = min(max((int)t0, 0), NIMG-1);
        int cls = (int)t1;

        const float* P = (lev==0) ? p0 : ((lev==1) ? p1 : p2);
        const float* plane = P + (size_t)(img*255 + a*85) * HW;
        const float* b0 = plane + gyc0 * W + gxc0;   // center
        const float* b1 = plane + gyc0 * W + gxc1;   // x-neighbor (same row)
        const float* b2 = plane + gyc1 * W + gxc0;   // y-neighbor (same col)

        // ---- class logits for up to 3 cells; lane covers c, c+32, c+64 ----
        float s0=0.f, s1=0.f, s2=0.f, p0v=0.f, p1v=0.f, p2v=0.f;
        #pragma unroll
        for (int i = 0; i < 3; i++){
            int c = lane + 32*i;
            if (c < NCLS){
                size_t o = (size_t)(5 + c) * HW;
                float v0 = __ldg(b0 + o);
                float v1 = fxv ? __ldg(b1 + o) : 0.f;
                float v2 = fyv ? __ldg(b2 + o) : 0.f;
                s0 += sp_(v0); if (c == cls) p0v = v0;
                if (fxv){ s1 += sp_(v1); if (c == cls) p1v = v1; }
                if (fyv){ s2 += sp_(v2); if (c == cls) p2v = v2; }
            }
        }
        // ---- box+obj logits: lanes 0-4 cell0, 8-12 cellx, 16-20 celly ----
        float opv = 0.f;
        if (lane < 5)                            opv = __ldg(b0 + (size_t)lane * HW);
        else if (lane >= 8  && lane < 13 && fxv) opv = __ldg(b1 + (size_t)(lane-8)  * HW);
        else if (lane >= 16 && lane < 21 && fyv) opv = __ldg(b2 + (size_t)(lane-16) * HW);

        s0 = wsum_(s0); p0v = wsum_(p0v);
        s1 = wsum_(s1); p1v = wsum_(p1v);
        s2 = wsum_(s2); p2v = wsum_(p2v);

        // ---- per-lane cell epilogue: lane k (0..2) owns cell k ----------
        int kk = (lane < 3) ? lane : 0;
        float q0 = __shfl_sync(FULLM, opv, kk*8 + 0);
        float q1 = __shfl_sync(FULLM, opv, kk*8 + 1);
        float q2 = __shfl_sync(FULLM, opv, kk*8 + 2);
        float q3 = __shfl_sync(FULLM, opv, kk*8 + 3);
        float xob= __shfl_sync(FULLM, opv, kk*8 + 4);

        bool kvalid = (lane == 0) || (lane == 1 && fxv) || (lane == 2 && fyv);
        float lb = 0.f, lc = 0.f, co = 0.f;

        if (kvalid){
            float gox = (kk == 1) ? (tx - (float)gx1) : remx;
            float goy = (kk == 2) ? (ty - (float)gy1) : remy;
            int   cx  = (kk == 1) ? gxc1 : gxc0;
            int   cy  = (kk == 2) ? gyc1 : gyc0;
            float ssum = (kk==0) ? s0 : ((kk==1) ? s1 : s2);
            float pick = (kk==0) ? p0v : ((kk==1) ? p1v : p2v);

            float px = sig_(q0) * 2.f - 0.5f;
            float py = sig_(q1) * 2.f - 0.5f;
            float sw = sig_(q2) * 2.f;
            float sh2= sig_(q3) * 2.f;
            float pw = sw * sw * aw;
            float ph = sh2 * sh2 * ah;
            float gi = giou_(px, py, pw, ph, gox, goy, tw, th);
            lb = 1.f - gi;
            lc = ssum - pick;

            float ov = fmaxf(gi, 0.f);
            if (ov > 0.f){
                int lvoff = (lev==0) ? 0 : ((lev==1) ? CELLS0 : (CELLS0+CELLS1));
                int cell = lvoff + (img*3 + a) * HW + cy * W + cx;
                unsigned old = atomicMax(&g_objmax[cell], __float_as_uint(ov));
                float oldf = __uint_as_float(old);
                if (ov > oldf){
                    co = (ov - oldf) * xob;          // telescopes to max*x
                    if (old == 0u) myCell = cell;    // first raiser lists cell
                }
            }
        }

        // warp-wide reductions (convergent; non-valid lanes contribute 0)
        lbox_c = wsum_(lb);
        cls_c  = wsum_(lc);
        corr_c = wsum_(co);
        cnt_c  = 1 + (fxv ? 1 : 0) + (fyv ? 1 : 0);
    }

    // ---- block reduction (blocks are level-homogeneous: 3072 % 8 == 0) ----
    __shared__ float sh_lb[8], sh_lc[8], sh_co[8];
    __shared__ int   sh_cn[8], sh_cell[8][3];
    if (lane == 0){
        sh_lb[wib] = lbox_c; sh_lc[wib] = cls_c; sh_co[wib] = corr_c;
        sh_cn[wib] = cnt_c;
    }
    if (lane < 3) sh_cell[wib][lane] = myCell;   // -1 when unused
    __syncthreads();
    if (tid == 0){
        int lev2 = gid / (MT * NA);
        float lb = 0.f, lc = 0.f, co = 0.f; int cn = 0, nv = 0;
        int cells[24];
        #pragma unroll
        for (int i = 0; i < 8; i++){
            lb += sh_lb[i]; lc += sh_lc[i]; co += sh_co[i]; cn += sh_cn[i];
            #pragma unroll
            for (int j = 0; j < 3; j++){
                int c = sh_cell[i][j];
                if (c >= 0) cells[nv++] = c;
            }
        }
        if (cn){
            atomicAdd(&g_acc[lev2],     (double)lb);
            atomicAdd(&g_acc[3 + lev2], (double)lc);
            atomicAdd(&g_cnt[lev2], cn);
        }
        if (co != 0.f) atomicAdd(&g_acc[9 + lev2], (double)co);
        if (nv){
            int bse = atomicAdd(&g_nflag, nv);
            for (int i = 0; i < nv; i++) g_cellList[bse + i] = cells[i];
        }
    }
}

// ============================ Kernel B ======================================
// 64 blocks: zero the listed g_objmax cells. g_nflag is read-only here.
__global__ __launch_bounds__(256) void k_zero()
{
    int n = min(g_nflag, TOTCELLS);
    for (int i = blockIdx.x * 256 + threadIdx.x; i < n; i += 64 * 256)
        g_objmax[g_cellList[i]] = 0u;
}

// ============================ Kernel C ======================================
// 1 warp: finalize scalar and reset all state (strictly after k_zero).
__global__ void k_fin(float* __restrict__ out)
{
    const int tid = threadIdx.x;
    if (tid == 0){
        const double cells[3] = {614400.0, 153600.0, 38400.0};
        const double bal[3]   = {4.0, 1.0, 0.4};
        double lbox = 0.0, lcls = 0.0, lobj = 0.0;
        #pragma unroll
        for (int l = 0; l < 3; l++){
            double cnt = (g_cnt[l] > 0) ? (double)g_cnt[l] : 1.0;
            lbox += g_acc[l] / cnt;
            lcls += g_acc[3 + l] / (cnt * (double)NCLS);
            lobj += ((g_acc[6 + l] - g_acc[9 + l]) / cells[l]) * bal[l];
        }
        out[0] = (float)((0.05 * lbox + 0.5 * lcls + lobj) * 32.0);
    }
    // reset state for next graph replay
    if (tid < 12) g_acc[tid] = 0.0;
    if (tid >= 12 && tid < 15) g_cnt[tid - 12] = 0;
    if (tid == 15) g_nflag = 0;
}

// ---------------------------------------------------------------------------
extern "C" void kernel_launch(void* const* d_in, const int* in_sizes, int n_in,
                              void* d_out, int out_size){
    const float* p0 = (const float*)d_in[0];
    const float* p1 = (const float*)d_in[1];
    const float* p2 = (const float*)d_in[2];
    const float* tg = (const float*)d_in[3];
    float* out = (float*)d_out;
    (void)in_sizes; (void)n_in; (void)out_size;

    k_main<<<GRID, 256>>>(p0, p1, p2, tg);
    k_zero<<<64, 256>>>();
    k_fin <<<1, 32>>>(out);
}

// round 16
// speedup vs baseline: 1.0820x; 1.0039x over previous
#include <cuda_runtime.h>

// ---------------------------------------------------------------------------
// ComputeLoss (YOLOv5-style), fixed shapes:
//   p0: (32,255,80,80)  p1: (32,255,40,40)  p2: (32,255,20,20)
//   targets: (1024,6) = [img, cls, cx, cy, w, h]
// Output: one float32 scalar.
//
// 2 launches:
//   k_main : CAND blocks first (low bids -> start long-latency gathers in
//            wave 1), dense softplus(obj) stream on high bids back-fills.
//            One warp per (lev,m,a) group; lanes 0/1/2 own the <=3 cells.
//   k_tail : 64 blocks zero listed g_objmax cells; last block (done-counter)
//            finalizes the scalar and resets all state.
// ---------------------------------------------------------------------------

#define NIMG 32
#define NA   3
#define NCLS 80
#define MT   1024
#define CELLS0 (NIMG*NA*80*80)    // 614400
#define CELLS1 (NIMG*NA*40*40)    // 153600
#define CELLS2 (NIMG*NA*20*20)    // 38400
#define CELLS_TOT (CELLS0+CELLS1+CELLS2)   // 806400
#define TOTCELLS (3*3*MT*3)       // list capacity: 3 cells per group max

#define OBJ_GROUPS (CELLS_TOT/4)              // 201600 float4 groups
#define OBJ_BLOCKS ((OBJ_GROUPS + 255)/256)   // 788
#define NGRP (3*MT*NA)                        // 9216 groups (lev,m,a)
#define CAND_BLOCKS (NGRP/8)                  // 1152
#define GRID (OBJ_BLOCKS + CAND_BLOCKS)       // 1940

#define TAIL_BLOCKS 64

#define FULLM 0xffffffffu

__constant__ float c_anch[3][3][2] = {
  {{1.25f,1.625f},{2.0f,3.75f},{4.125f,2.875f}},
  {{1.875f,3.8125f},{3.875f,2.8125f},{3.6875f,7.4375f}},
  {{3.625f,2.8125f},{4.875f,6.1875f},{11.65625f,10.1875f}}
};

// per-cell objectness max (float bits >= 0). Zero at module load; k_tail
// zeroes every touched cell each launch (list-driven).
__device__ unsigned g_objmax[CELLS_TOT];
__device__ int   g_cellList[TOTCELLS];
__device__ int   g_nflag;
__device__ int   g_done;
// [0..2]=lbox, [3..5]=cls, [6..8]=obj_softplus, [9..11]=obj_corr
__device__ double g_acc[12];
__device__ int g_cnt[3];

__device__ __forceinline__ float sp_(float x){          // softplus (fast-math)
    return fmaxf(x, 0.f) + __logf(1.f + __expf(-fabsf(x)));
}
__device__ __forceinline__ float sig_(float x){
    return 1.f / (1.f + __expf(-x));
}

__device__ __forceinline__ float giou_(float px,float py,float pw,float ph,
                                       float gx,float gy,float gw,float gh){
    const float eps = 1e-7f;
    float px1 = px - pw*0.5f, py1 = py - ph*0.5f;
    float px2 = px + pw*0.5f, py2 = py + ph*0.5f;
    float qx1 = gx - gw*0.5f, qy1 = gy - gh*0.5f;
    float qx2 = gx + gw*0.5f, qy2 = gy + gh*0.5f;
    float iw = fmaxf(fminf(px2,qx2) - fmaxf(px1,qx1), 0.f);
    float ih = fmaxf(fminf(py2,qy2) - fmaxf(py1,qy1), 0.f);
    float inter = iw * ih;
    float uni = pw*ph + gw*gh - inter + eps;
    float iou = inter / uni;
    float cw = fmaxf(px2,qx2) - fminf(px1,qx1);
    float ch = fmaxf(py2,qy2) - fminf(py1,qy1);
    float ca = cw*ch + eps;
    return iou - (ca - uni) / ca;
}

// warp butterfly sum (warp-wide, convergent)
__device__ __forceinline__ float wsum_(float v){
    #pragma unroll
    for (int d = 16; d; d >>= 1) v += __shfl_xor_sync(FULLM, v, d);
    return v;
}

// ============================ Kernel A ======================================
__global__ __launch_bounds__(256, 6) void k_main(
        const float* __restrict__ p0, const float* __restrict__ p1,
        const float* __restrict__ p2, const float* __restrict__ tg)
{
    const int tid  = threadIdx.x;
    const int lane = tid & 31;
    const int wib  = tid >> 5;

    if (blockIdx.x >= CAND_BLOCKS){
        // ---------------- dense objectness softplus sum -------------------
        // scheduled AFTER cand blocks; fills latency bubbles at the end.
        // warps are level-homogeneous (boundaries at multiples of 32)
        int g = (blockIdx.x - CAND_BLOCKS) * 256 + tid;
        float s = 0.f;
        int lev = 2;
        if (g < OBJ_GROUPS){
            int cell = g * 4;
            int base, HW;
            const float* P;
            if (cell < CELLS0){ lev = 0; base = cell;               HW = 6400; P = p0; }
            else if (cell < CELLS0 + CELLS1){ lev = 1; base = cell - CELLS0; HW = 1600; P = p1; }
            else { lev = 2; base = cell - (CELLS0 + CELLS1); HW = 400; P = p2; }
            int n_a = base / HW, hw = base - n_a * HW;
            int n = n_a / 3, a = n_a - n * 3;
            const float4 v = *reinterpret_cast<const float4*>(
                P + (size_t)(n*255 + a*85 + 4) * HW + hw);
            s = sp_(v.x) + sp_(v.y) + sp_(v.z) + sp_(v.w);
        }
        s = wsum_(s);
        __shared__ float sh[8];
        if (lane == 0) sh[wib] = s;
        __syncthreads();
        if (tid == 0){
            float t = sh[0]+sh[1]+sh[2]+sh[3]+sh[4]+sh[5]+sh[6]+sh[7];
            atomicAdd(&g_acc[6 + lev], (double)t);
        }
        return;
    }

    // ---------- candidate path: ONE WARP PER (lev, m, a) GROUP ------------
    int gid = (blockIdx.x * 256 + tid) >> 5;   // 0..9215
    int lev = gid / (MT * NA);
    int r   = gid - lev * (MT * NA);
    int m   = r / NA;
    int a   = r - m * NA;

    const int W  = (lev==0) ? 80 : ((lev==1) ? 40 : 20);
    const int HW = W * W;
    const float fW = (float)W;

    float t0 = tg[m*6+0];
    float t1 = tg[m*6+1];
    float tx = tg[m*6+2] * fW;
    float ty = tg[m*6+3] * fW;
    float tw = tg[m*6+4] * fW;
    float th = tg[m*6+5] * fW;

    float aw = c_anch[lev][a][0];
    float ah = c_anch[lev][a][1];
    float rw = aw / tw, rh = ah / th;
    float mr = fmaxf(fmaxf(rw, 1.f/rw), fmaxf(rh, 1.f/rh));
    bool bm = mr < 4.0f;    // warp-uniform

    float lbox_c = 0.f, cls_c = 0.f, corr_c = 0.f;
    int cnt_c = 0;
    int myCell = -1;        // lanes 0-2: listed cell (first raiser) or -1

    if (bm){   // warp-uniform branch: all lanes enter together
        int gx0 = (int)floorf(tx);
        int gy0 = (int)floorf(ty);
        float remx = tx - (float)gx0;
        float remy = ty - (float)gy0;

        // x neighbor: exactly one of left/right may fire (rem==0.5 -> none)
        bool xleft = remx < 0.5f;
        bool fxv = xleft ? (tx > 1.0f) : ((remx > 0.5f) && (tx < fW - 1.0f));
        int  gx1 = xleft ? gx0 - 1 : gx0 + 1;
        // y neighbor
        bool ytop = remy < 0.5f;
        bool fyv = ytop ? (ty > 1.0f) : ((remy > 0.5f) && (ty < fW - 1.0f));
        int  gy1 = ytop ? gy0 - 1 : gy0 + 1;

        int gxc0 = min(max(gx0, 0), W-1), gyc0 = min(max(gy0, 0), W-1);
        int gxc1 = min(max(gx1, 0), W-1), gyc1 = min(max(gy1, 0), W-1);
        int img = min(max((int)t0, 0), NIMG-1);
        int cls = (int)t1;

        const float* P = (lev==0) ? p0 : ((lev==1) ? p1 : p2);
        const float* plane = P + (size_t)(img*255 + a*85) * HW;
        const float* b0 = plane + gyc0 * W + gxc0;   // center
        const float* b1 = plane + gyc0 * W + gxc1;   // x-neighbor (same row)
        const float* b2 = plane + gyc1 * W + gxc0;   // y-neighbor (same col)

        // ---- class logits for up to 3 cells; lane covers c, c+32, c+64 ----
        float s0=0.f, s1=0.f, s2=0.f, p0v=0.f, p1v=0.f, p2v=0.f;
        #pragma unroll
        for (int i = 0; i < 3; i++){
            int c = lane + 32*i;
            if (c < NCLS){
                size_t o = (size_t)(5 + c) * HW;
                float v0 = __ldg(b0 + o);
                float v1 = fxv ? __ldg(b1 + o) : 0.f;
                float v2 = fyv ? __ldg(b2 + o) : 0.f;
                s0 += sp_(v0); if (c == cls) p0v = v0;
                if (fxv){ s1 += sp_(v1); if (c == cls) p1v = v1; }
                if (fyv){ s2 += sp_(v2); if (c == cls) p2v = v2; }
            }
        }
        // ---- box+obj logits: lanes 0-4 cell0, 8-12 cellx, 16-20 celly ----
        float opv = 0.f;
        if (lane < 5)                            opv = __ldg(b0 + (size_t)lane * HW);
        else if (lane >= 8  && lane < 13 && fxv) opv = __ldg(b1 + (size_t)(lane-8)  * HW);
        else if (lane >= 16 && lane < 21 && fyv) opv = __ldg(b2 + (size_t)(lane-16) * HW);

        s0 = wsum_(s0); p0v = wsum_(p0v);
        s1 = wsum_(s1); p1v = wsum_(p1v);
        s2 = wsum_(s2); p2v = wsum_(p2v);

        // ---- per-lane cell epilogue: lane k (0..2) owns cell k ----------
        int kk = (lane < 3) ? lane : 0;
        float q0 = __shfl_sync(FULLM, opv, kk*8 + 0);
        float q1 = __shfl_sync(FULLM, opv, kk*8 + 1);
        float q2 = __shfl_sync(FULLM, opv, kk*8 + 2);
        float q3 = __shfl_sync(FULLM, opv, kk*8 + 3);
        float xob= __shfl_sync(FULLM, opv, kk*8 + 4);

        bool kvalid = (lane == 0) || (lane == 1 && fxv) || (lane == 2 && fyv);
        float lb = 0.f, lc = 0.f, co = 0.f;

        if (kvalid){
            float gox = (kk == 1) ? (tx - (float)gx1) : remx;
            float goy = (kk == 2) ? (ty - (float)gy1) : remy;
            int   cx  = (kk == 1) ? gxc1 : gxc0;
            int   cy  = (kk == 2) ? gyc1 : gyc0;
            float ssum = (kk==0) ? s0 : ((kk==1) ? s1 : s2);
            float pick = (kk==0) ? p0v : ((kk==1) ? p1v : p2v);

            float px = sig_(q0) * 2.f - 0.5f;
            float py = sig_(q1) * 2.f - 0.5f;
            float sw = sig_(q2) * 2.f;
            float sh2= sig_(q3) * 2.f;
            float pw = sw * sw * aw;
            float ph = sh2 * sh2 * ah;
            float gi = giou_(px, py, pw, ph, gox, goy, tw, th);
            lb = 1.f - gi;
            lc = ssum - pick;

            float ov = fmaxf(gi, 0.f);
            if (ov > 0.f){
                int lvoff = (lev==0) ? 0 : ((lev==1) ? CELLS0 : (CELLS0+CELLS1));
                int cell = lvoff + (img*3 + a) * HW + cy * W + cx;
                unsigned old = atomicMax(&g_objmax[cell], __float_as_uint(ov));
                float oldf = __uint_as_float(old);
                if (ov > oldf){
                    co = (ov - oldf) * xob;          // telescopes to max*x
                    if (old == 0u) myCell = cell;    // first raiser lists cell
                }
            }
        }

        // warp-wide reductions (convergent; non-valid lanes contribute 0)
        lbox_c = wsum_(lb);
        cls_c  = wsum_(lc);
        corr_c = wsum_(co);
        cnt_c  = 1 + (fxv ? 1 : 0) + (fyv ? 1 : 0);
    }

    // ---- block reduction (blocks are level-homogeneous: 3072 % 8 == 0) ----
    __shared__ float sh_lb[8], sh_lc[8], sh_co[8];
    __shared__ int   sh_cn[8], sh_cell[8][3];
    if (lane == 0){
        sh_lb[wib] = lbox_c; sh_lc[wib] = cls_c; sh_co[wib] = corr_c;
        sh_cn[wib] = cnt_c;
    }
    if (lane < 3) sh_cell[wib][lane] = myCell;   // -1 when unused
    __syncthreads();
    if (tid == 0){
        int lev2 = gid / (MT * NA);
        float lb = 0.f, lc = 0.f, co = 0.f; int cn = 0, nv = 0;
        int cells[24];
        #pragma unroll
        for (int i = 0; i < 8; i++){
            lb += sh_lb[i]; lc += sh_lc[i]; co += sh_co[i]; cn += sh_cn[i];
            #pragma unroll
            for (int j = 0; j < 3; j++){
                int c = sh_cell[i][j];
                if (c >= 0) cells[nv++] = c;
            }
        }
        if (cn){
            atomicAdd(&g_acc[lev2],     (double)lb);
            atomicAdd(&g_acc[3 + lev2], (double)lc);
            atomicAdd(&g_cnt[lev2], cn);
        }
        if (co != 0.f) atomicAdd(&g_acc[9 + lev2], (double)co);
        if (nv){
            int bse = atomicAdd(&g_nflag, nv);
            for (int i = 0; i < nv; i++) g_cellList[bse + i] = cells[i];
        }
    }
}

// ============================ Kernel B ======================================
// 64 blocks: zero listed cells; last block finalizes scalar + resets state.
__global__ __launch_bounds__(256) void k_tail(float* __restrict__ out)
{
    const int tid = threadIdx.x;
    int n = min(g_nflag, TOTCELLS);   // read BEFORE any reset

    for (int i = blockIdx.x * 256 + tid; i < n; i += TAIL_BLOCKS * 256)
        g_objmax[g_cellList[i]] = 0u;

    __syncthreads();
    __shared__ int s_last;
    if (tid == 0){
        __threadfence();   // publish this block's zeroing before done-mark
        s_last = (atomicAdd(&g_done, 1) == TAIL_BLOCKS - 1) ? 1 : 0;
    }
    __syncthreads();
    if (s_last && tid == 0){
        const double cells[3] = {614400.0, 153600.0, 38400.0};
        const double bal[3]   = {4.0, 1.0, 0.4};
        double lbox = 0.0, lcls = 0.0, lobj = 0.0;
        #pragma unroll
        for (int l = 0; l < 3; l++){
            double cnt = (g_cnt[l] > 0) ? (double)g_cnt[l] : 1.0;
            lbox += g_acc[l] / cnt;
            lcls += g_acc[3 + l] / (cnt * (double)NCLS);
            lobj += ((g_acc[6 + l] - g_acc[9 + l]) / cells[l]) * bal[l];
        }
        out[0] = (float)((0.05 * lbox + 0.5 * lcls + lobj) * 32.0);
        // reset all state for next graph replay
        #pragma unroll
        for (int j = 0; j < 12; j++) g_acc[j] = 0.0;
        g_cnt[0] = g_cnt[1] = g_cnt[2] = 0;
        g_nflag = 0;
        g_done  = 0;
    }
}

// ---------------------------------------------------------------------------
extern "C" void kernel_launch(void* const* d_in, const int* in_sizes, int n_in,
                              void* d_out, int out_size){
    const float* p0 = (const float*)d_in[0];
    const float* p1 = (const float*)d_in[1];
    const float* p2 = (const float*)d_in[2];
    const float* tg = (const float*)d_in[3];
    float* out = (float*)d_out;
    (void)in_sizes; (void)n_in; (void)out_size;

    k_main<<<GRID, 256>>>(p0, p1, p2, tg);
    k_tail<<<TAIL_BLOCKS, 256>>>(out);
}

// round 17
// speedup vs baseline: 1.2422x; 1.1480x over previous
#include <cuda_runtime.h>

// ---------------------------------------------------------------------------
// ComputeLoss (YOLOv5-style), fixed shapes:
//   p0: (32,255,80,80)  p1: (32,255,40,40)  p2: (32,255,20,20)
//   targets: (1024,6) = [img, cls, cx, cy, w, h]
// Output: one float32 scalar.
//
// 2 launches:
//   k_main : CAND blocks first (long-latency gathers start in wave 1), dense
//            softplus(obj) stream back-fills. One warp per (lev,m,a) group;
//            lanes 0/1/2 own the <=3 flagged cells.
//            Scatter-max uses EPOCH-TAGGED 64-bit atomicMax: value =
//            (epoch<<32)|float_bits(ov). Stale-epoch entries lose
//            automatically, so NO reset pass is ever needed.
//   k_tail : 1 block — finalize scalar, reset accumulators, epoch++.
// ---------------------------------------------------------------------------

#define NIMG 32
#define NA   3
#define NCLS 80
#define MT   1024
#define CELLS0 (NIMG*NA*80*80)    // 614400
#define CELLS1 (NIMG*NA*40*40)    // 153600
#define CELLS2 (NIMG*NA*20*20)    // 38400
#define CELLS_TOT (CELLS0+CELLS1+CELLS2)   // 806400

#define OBJ_GROUPS (CELLS_TOT/4)              // 201600 float4 groups
#define OBJ_BLOCKS ((OBJ_GROUPS + 255)/256)   // 788
#define NGRP (3*MT*NA)                        // 9216 groups (lev,m,a)
#define CAND_BLOCKS (NGRP/8)                  // 1152
#define GRID (OBJ_BLOCKS + CAND_BLOCKS)       // 1940

#define FULLM 0xffffffffu

__constant__ float c_anch[3][3][2] = {
  {{1.25f,1.625f},{2.0f,3.75f},{4.125f,2.875f}},
  {{1.875f,3.8125f},{3.875f,2.8125f},{3.6875f,7.4375f}},
  {{3.625f,2.8125f},{4.875f,6.1875f},{11.65625f,10.1875f}}
};

// epoch-tagged per-cell objectness max: (epoch << 32) | float_bits(ov>=0).
// Entries from older epochs always lose to current-epoch writes, so the
// array never needs resetting across launches/replays.
__device__ unsigned long long g_objmax[CELLS_TOT];
__device__ int g_epoch = 1;
// [0..2]=lbox, [3..5]=cls, [6..8]=obj_softplus, [9..11]=obj_corr
__device__ double g_acc[12];
__device__ int g_cnt[3];

__device__ __forceinline__ float sp_(float x){          // softplus (fast-math)
    return fmaxf(x, 0.f) + __logf(1.f + __expf(-fabsf(x)));
}
__device__ __forceinline__ float sig_(float x){
    return 1.f / (1.f + __expf(-x));
}

__device__ __forceinline__ float giou_(float px,float py,float pw,float ph,
                                       float gx,float gy,float gw,float gh){
    const float eps = 1e-7f;
    float px1 = px - pw*0.5f, py1 = py - ph*0.5f;
    float px2 = px + pw*0.5f, py2 = py + ph*0.5f;
    float qx1 = gx - gw*0.5f, qy1 = gy - gh*0.5f;
    float qx2 = gx + gw*0.5f, qy2 = gy + gh*0.5f;
    float iw = fmaxf(fminf(px2,qx2) - fmaxf(px1,qx1), 0.f);
    float ih = fmaxf(fminf(py2,qy2) - fmaxf(py1,qy1), 0.f);
    float inter = iw * ih;
    float uni = pw*ph + gw*gh - inter + eps;
    float iou = inter / uni;
    float cw = fmaxf(px2,qx2) - fminf(px1,qx1);
    float ch = fmaxf(py2,qy2) - fminf(py1,qy1);
    float ca = cw*ch + eps;
    return iou - (ca - uni) / ca;
}

// warp butterfly sum (warp-wide, convergent)
__device__ __forceinline__ float wsum_(float v){
    #pragma unroll
    for (int d = 16; d; d >>= 1) v += __shfl_xor_sync(FULLM, v, d);
    return v;
}

// ============================ Kernel A ======================================
__global__ __launch_bounds__(256, 6) void k_main(
        const float* __restrict__ p0, const float* __restrict__ p1,
        const float* __restrict__ p2, const float* __restrict__ tg)
{
    const int tid  = threadIdx.x;
    const int lane = tid & 31;
    const int wib  = tid >> 5;

    if (blockIdx.x >= CAND_BLOCKS){
        // ---------------- dense objectness softplus sum -------------------
        // scheduled AFTER cand blocks; fills latency bubbles at the end.
        int g = (blockIdx.x - CAND_BLOCKS) * 256 + tid;
        float s = 0.f;
        int lev = 2;
        if (g < OBJ_GROUPS){
            int cell = g * 4;
            int base, HW;
            const float* P;
            if (cell < CELLS0){ lev = 0; base = cell;               HW = 6400; P = p0; }
            else if (cell < CELLS0 + CELLS1){ lev = 1; base = cell - CELLS0; HW = 1600; P = p1; }
            else { lev = 2; base = cell - (CELLS0 + CELLS1); HW = 400; P = p2; }
            int n_a = base / HW, hw = base - n_a * HW;
            int n = n_a / 3, a = n_a - n * 3;
            const float4 v = *reinterpret_cast<const float4*>(
                P + (size_t)(n*255 + a*85 + 4) * HW + hw);
            s = sp_(v.x) + sp_(v.y) + sp_(v.z) + sp_(v.w);
        }
        s = wsum_(s);
        __shared__ float sh[8];
        if (lane == 0) sh[wib] = s;
        __syncthreads();
        if (tid == 0){
            float t = sh[0]+sh[1]+sh[2]+sh[3]+sh[4]+sh[5]+sh[6]+sh[7];
            atomicAdd(&g_acc[6 + lev], (double)t);
        }
        return;
    }

    // ---------- candidate path: ONE WARP PER (lev, m, a) GROUP ------------
    int gid = (blockIdx.x * 256 + tid) >> 5;   // 0..9215
    int lev = gid / (MT * NA);
    int r   = gid - lev * (MT * NA);
    int m   = r / NA;
    int a   = r - m * NA;

    const int W  = (lev==0) ? 80 : ((lev==1) ? 40 : 20);
    const int HW = W * W;
    const float fW = (float)W;

    float t0 = tg[m*6+0];
    float t1 = tg[m*6+1];
    float tx = tg[m*6+2] * fW;
    float ty = tg[m*6+3] * fW;
    float tw = tg[m*6+4] * fW;
    float th = tg[m*6+5] * fW;

    float aw = c_anch[lev][a][0];
    float ah = c_anch[lev][a][1];
    float rw = aw / tw, rh = ah / th;
    float mr = fmaxf(fmaxf(rw, 1.f/rw), fmaxf(rh, 1.f/rh));
    bool bm = mr < 4.0f;    // warp-uniform

    float lbox_c = 0.f, cls_c = 0.f, corr_c = 0.f;
    int cnt_c = 0;

    if (bm){   // warp-uniform branch: all lanes enter together
        int gx0 = (int)floorf(tx);
        int gy0 = (int)floorf(ty);
        float remx = tx - (float)gx0;
        float remy = ty - (float)gy0;

        // x neighbor: exactly one of left/right may fire (rem==0.5 -> none)
        bool xleft = remx < 0.5f;
        bool fxv = xleft ? (tx > 1.0f) : ((remx > 0.5f) && (tx < fW - 1.0f));
        int  gx1 = xleft ? gx0 - 1 : gx0 + 1;
        // y neighbor
        bool ytop = remy < 0.5f;
        bool fyv = ytop ? (ty > 1.0f) : ((remy > 0.5f) && (ty < fW - 1.0f));
        int  gy1 = ytop ? gy0 - 1 : gy0 + 1;

        int gxc0 = min(max(gx0, 0), W-1), gyc0 = min(max(gy0, 0), W-1);
        int gxc1 = min(max(gx1, 0), W-1), gyc1 = min(max(gy1, 0), W-1);
        int img = min(max((int)t0, 0), NIMG-1);
        int cls = (int)t1;

        const float* P = (lev==0) ? p0 : ((lev==1) ? p1 : p2);
        const float* plane = P + (size_t)(img*255 + a*85) * HW;
        const float* b0 = plane + gyc0 * W + gxc0;   // center
        const float* b1 = plane + gyc0 * W + gxc1;   // x-neighbor (same row)
        const float* b2 = plane + gyc1 * W + gxc0;   // y-neighbor (same col)

        // ---- class logits for up to 3 cells; lane covers c, c+32, c+64 ----
        float s0=0.f, s1=0.f, s2=0.f, p0v=0.f, p1v=0.f, p2v=0.f;
        #pragma unroll
        for (int i = 0; i < 3; i++){
            int c = lane + 32*i;
            if (c < NCLS){
                size_t o = (size_t)(5 + c) * HW;
                float v0 = __ldg(b0 + o);
                float v1 = fxv ? __ldg(b1 + o) : 0.f;
                float v2 = fyv ? __ldg(b2 + o) : 0.f;
                s0 += sp_(v0); if (c == cls) p0v = v0;
                if (fxv){ s1 += sp_(v1); if (c == cls) p1v = v1; }
                if (fyv){ s2 += sp_(v2); if (c == cls) p2v = v2; }
            }
        }
        // ---- box+obj logits: lanes 0-4 cell0, 8-12 cellx, 16-20 celly ----
        float opv = 0.f;
        if (lane < 5)                            opv = __ldg(b0 + (size_t)lane * HW);
        else if (lane >= 8  && lane < 13 && fxv) opv = __ldg(b1 + (size_t)(lane-8)  * HW);
        else if (lane >= 16 && lane < 21 && fyv) opv = __ldg(b2 + (size_t)(lane-16) * HW);

        s0 = wsum_(s0); p0v = wsum_(p0v);
        s1 = wsum_(s1); p1v = wsum_(p1v);
        s2 = wsum_(s2); p2v = wsum_(p2v);

        // ---- per-lane cell epilogue: lane k (0..2) owns cell k ----------
        int kk = (lane < 3) ? lane : 0;
        float q0 = __shfl_sync(FULLM, opv, kk*8 + 0);
        float q1 = __shfl_sync(FULLM, opv, kk*8 + 1);
        float q2 = __shfl_sync(FULLM, opv, kk*8 + 2);
        float q3 = __shfl_sync(FULLM, opv, kk*8 + 3);
        float xob= __shfl_sync(FULLM, opv, kk*8 + 4);

        bool kvalid = (lane == 0) || (lane == 1 && fxv) || (lane == 2 && fyv);
        float lb = 0.f, lc = 0.f, co = 0.f;

        if (kvalid){
            float gox = (kk == 1) ? (tx - (float)gx1) : remx;
            float goy = (kk == 2) ? (ty - (float)gy1) : remy;
            int   cx  = (kk == 1) ? gxc1 : gxc0;
            int   cy  = (kk == 2) ? gyc1 : gyc0;
            float ssum = (kk==0) ? s0 : ((kk==1) ? s1 : s2);
            float pick = (kk==0) ? p0v : ((kk==1) ? p1v : p2v);

            float px = sig_(q0) * 2.f - 0.5f;
            float py = sig_(q1) * 2.f - 0.5f;
            float sw = sig_(q2) * 2.f;
            float sh2= sig_(q3) * 2.f;
            float pw = sw * sw * aw;
            float ph = sh2 * sh2 * ah;
            float gi = giou_(px, py, pw, ph, gox, goy, tw, th);
            lb = 1.f - gi;
            lc = ssum - pick;

            float ov = fmaxf(gi, 0.f);
            if (ov > 0.f){
                int lvoff = (lev==0) ? 0 : ((lev==1) ? CELLS0 : (CELLS0+CELLS1));
                int cell = lvoff + (img*3 + a) * HW + cy * W + cx;
                unsigned long long ep = (unsigned long long)g_epoch;
                unsigned long long want = (ep << 32) | (unsigned long long)__float_as_uint(ov);
                unsigned long long old = atomicMax(&g_objmax[cell], want);
                if (want > old){
                    // stale-epoch baseline is 0; same-epoch baseline is its ov
                    float oldf = ((old >> 32) == ep)
                               ? __uint_as_float((unsigned)(old & 0xffffffffu)) : 0.f;
                    co = (ov - oldf) * xob;          // telescopes to max*x
                }
            }
        }

        // warp-wide reductions (convergent; non-valid lanes contribute 0)
        lbox_c = wsum_(lb);
        cls_c  = wsum_(lc);
        corr_c = wsum_(co);
        cnt_c  = 1 + (fxv ? 1 : 0) + (fyv ? 1 : 0);
    }

    // ---- block reduction (blocks are level-homogeneous: 3072 % 8 == 0) ----
    __shared__ float sh_lb[8], sh_lc[8], sh_co[8];
    __shared__ int   sh_cn[8];
    if (lane == 0){
        sh_lb[wib] = lbox_c; sh_lc[wib] = cls_c; sh_co[wib] = corr_c;
        sh_cn[wib] = cnt_c;
    }
    __syncthreads();
    if (tid == 0){
        int lev2 = gid / (MT * NA);
        float lb = 0.f, lc = 0.f, co = 0.f; int cn = 0;
        #pragma unroll
        for (int i = 0; i < 8; i++){
            lb += sh_lb[i]; lc += sh_lc[i]; co += sh_co[i]; cn += sh_cn[i];
        }
        if (cn){
            atomicAdd(&g_acc[lev2],     (double)lb);
            atomicAdd(&g_acc[3 + lev2], (double)lc);
            atomicAdd(&g_cnt[lev2], cn);
        }
        if (co != 0.f) atomicAdd(&g_acc[9 + lev2], (double)co);
    }
}

// ============================ Kernel B ======================================
// 1 block: finalize scalar, reset accumulators, bump epoch (invalidates all
// g_objmax entries for the next launch — no zeroing pass needed).
__global__ void k_tail(float* __restrict__ out)
{
    const int tid = threadIdx.x;
    if (tid == 0){
        const double cells[3] = {614400.0, 153600.0, 38400.0};
        const double bal[3]   = {4.0, 1.0, 0.4};
        double lbox = 0.0, lcls = 0.0, lobj = 0.0;
        #pragma unroll
        for (int l = 0; l < 3; l++){
            double cnt = (g_cnt[l] > 0) ? (double)g_cnt[l] : 1.0;
            lbox += g_acc[l] / cnt;
            lcls += g_acc[3 + l] / (cnt * (double)NCLS);
            lobj += ((g_acc[6 + l] - g_acc[9 + l]) / cells[l]) * bal[l];
        }
        out[0] = (float)((0.05 * lbox + 0.5 * lcls + lobj) * 32.0);
        g_epoch = g_epoch + 1;   // retire all scatter-max entries
    }
    if (tid < 12) g_acc[tid] = 0.0;
    if (tid >= 12 && tid < 15) g_cnt[tid - 12] = 0;
}

// ---------------------------------------------------------------------------
extern "C" void kernel_launch(void* const* d_in, const int* in_sizes, int n_in,
                              void* d_out, int out_size){
    const float* p0 = (const float*)d_in[0];
    const float* p1 = (const float*)d_in[1];
    const float* p2 = (const float*)d_in[2];
    const float* tg = (const float*)d_in[3];
    float* out = (float*)d_out;
    (void)in_sizes; (void)n_in; (void)out_size;

    k_main<<<GRID, 256>>>(p0, p1, p2, tg);
    k_tail<<<1, 32>>>(out);
}